// round 14
// baseline (speedup 1.0000x reference)
#include <cuda_runtime.h>

#define TT   1024
#define FF   2048
#define LL   128
#define HH   256
#define GG   384
#define NF   14            // features per CTA (7 pairs)
#define NTH  256
#define NCTA 147           // ceil(2048/14), one CTA per SM
#define PSTR 10            // pair-stride in u64 (7 pairs + 3 pad, 80B rows)

typedef unsigned long long u64;

// transposed weights, padded for prefetch-ring overrun (no allocation)
__device__ float g_W1t[LL * HH + 2048];    // [k][j]       = W1[j][k]
__device__ float g_W2t[HH * LL + 2048];    // [j][k']      = W2[k'][j]
__device__ float g_Wht2[LL * 512 + 2048];  // [k][p][4]    = {Whh[p][k], Whh[p+128][k], Whh[p+256][k], 0}

// shared-memory layout (u64 units)
#define OFF_HS   0                          // h: [k=128][10]   -> 1280
#define OFF_A1   1280                       // A1: [j=256][10]  -> 2560
#define OFF_SC   3840                       // partial scratch (8-u64 col slots)
#define A_BLK    2048                       // A: [kq=4][col=256][8]
#define B_BLK    1024                       // B: [je=8][col=128][8]
#define C_BLK    3072                       // C: [kh=2][col=384][8]
#define U64_CNT  12032
#define SMEM_BYTES (U64_CNT * 8 + 64 * 4)   // 96512 B

__device__ __forceinline__ u64 pk2(float lo, float hi) {
    u64 r; asm("mov.b64 %0, {%1, %2};" : "=l"(r) : "f"(lo), "f"(hi)); return r;
}
__device__ __forceinline__ float2 up2(u64 v) {
    float2 r; asm("mov.b64 {%0, %1}, %2;" : "=f"(r.x), "=f"(r.y) : "l"(v)); return r;
}
__device__ __forceinline__ u64 fma2(u64 a, u64 b, u64 c) {
    u64 d; asm("fma.rn.f32x2 %0, %1, %2, %3;" : "=l"(d) : "l"(a), "l"(b), "l"(c)); return d;
}
__device__ __forceinline__ u64 add2(u64 a, u64 b) {
    u64 d; asm("add.rn.f32x2 %0, %1, %2;" : "=l"(d) : "l"(a), "l"(b)); return d;
}
__device__ __forceinline__ float sigm(float x) { return 1.0f / (1.0f + expf(-x)); }

__global__ void prep_kernel(const float* __restrict__ W1,
                            const float* __restrict__ W2,
                            const float* __restrict__ Whh) {
    int i = blockIdx.x * blockDim.x + threadIdx.x;
    if (i < HH * LL) { int j = i / LL, k = i % LL; g_W1t[k * HH + j] = W1[i]; }
    if (i < LL * HH) { int k = i / HH, j = i % HH; g_W2t[j * LL + k] = W2[i]; }
    if (i < LL * 512) {
        int k = i >> 9, r = i & 511, p = r >> 2, c = r & 3;
        g_Wht2[i] = (c < 3) ? Whh[(c * LL + p) * LL + k] : 0.0f;
    }
}

__global__ __launch_bounds__(NTH, 1)
void odernn_kernel(const float* __restrict__ times,
                   const float* __restrict__ vals,
                   const float* __restrict__ mask,
                   const float* __restrict__ b1,
                   const float* __restrict__ b2,
                   const float* __restrict__ Wih,
                   const float* __restrict__ bih,
                   const float* __restrict__ bhh,
                   float* __restrict__ out)
{
    extern __shared__ u64 sm[];
    float* xob = (float*)(sm + U64_CNT);     // 16
    float* xms = (float*)(sm + U64_CNT) + 16;

    const int tid = threadIdx.x;
    const int cta = blockIdx.x;

    for (int i = tid; i < 128 * PSTR; i += NTH) sm[OFF_HS + i] = 0ull;   // h0 = 0

    // thread-resident role constants
    const int qA  = tid & 63;            // phase-A col-quad (cols 4qA..4qA+3 of 256)
    const int kqA = tid >> 6;            // phase-A k-quarter (0..3)
    const int qB  = tid & 31;            // phase-B col-quad (cols 4qB..4qB+3 of 128)
    const int je  = tid >> 5;            // phase-B j-eighth (0..7)
    const int p   = tid & 127;           // latent index (C / GRU)
    const int kh  = tid >> 7;            // phase-C k-half
    const int fh  = tid >> 7;            // GRU feature-subset selector
    const float bbA = __ldg(b1 + tid);
    const float bbO = __ldg(b2 + (tid >> 1));
    const float brg = __ldg(bhh + p), bzg = __ldg(bhh + p + 128), bng = __ldg(bhh + p + 256);
    const float wir = __ldg(Wih + p), wiz = __ldg(Wih + p + 128), win = __ldg(Wih + p + 256);
    const float bir = __ldg(bih + p), biz = __ldg(bih + p + 128), binn = __ldg(bih + p + 256);
    __syncthreads();

    for (int t = 0; t < TT; t++) {
        if (tid < 16) {
            int fg = cta * NF + tid;
            float xo = 0.0f, xm = 0.0f;
            if (tid < NF && fg < FF) {
                long it = (long)(TT - 1 - t) * FF + fg;
                xo = __ldg(vals + it);
                xm = __ldg(mask + it);
            }
            xob[tid] = xo; xms[tid] = xm;
        }
        float dt = 0.0f;
        if (t > 0) dt = __ldg(times + (TT - t)) - __ldg(times + (TT - 1 - t));

        // ---- Phase A: partial a1[f][4qA..] = sum_{k in quarter} h[f][k]*W1t[k][4qA..]
        {
            const int k0 = kqA * 32;
            const float4* w = (const float4*)g_W1t + qA;   // + k*64
            float4 buf[4];
            #pragma unroll
            for (int u = 0; u < 4; u++) buf[u] = __ldg(w + (k0 + u) * 64);
            u64 ac[4][7];
            #pragma unroll
            for (int c = 0; c < 4; c++)
                #pragma unroll
                for (int i = 0; i < 7; i++) ac[c][i] = 0ull;
            for (int kk = 0; kk < 32; kk += 4) {
                #pragma unroll
                for (int u = 0; u < 4; u++) {
                    float4 wv = buf[u];
                    buf[u] = __ldg(w + (k0 + kk + u + 4) * 64);   // ring prefetch (padded)
                    u64 wd[4] = { pk2(wv.x, wv.x), pk2(wv.y, wv.y),
                                  pk2(wv.z, wv.z), pk2(wv.w, wv.w) };
                    const u64* hr = sm + OFF_HS + (k0 + kk + u) * PSTR;
                    ulonglong2 t0 = *(const ulonglong2*)hr;
                    ulonglong2 t1 = *(const ulonglong2*)(hr + 2);
                    ulonglong2 t2 = *(const ulonglong2*)(hr + 4);
                    u64 hv[7] = { t0.x, t0.y, t1.x, t1.y, t2.x, t2.y, hr[6] };
                    #pragma unroll
                    for (int c = 0; c < 4; c++)
                        #pragma unroll
                        for (int i = 0; i < 7; i++) ac[c][i] = fma2(hv[i], wd[c], ac[c][i]);
                }
            }
            #pragma unroll
            for (int c = 0; c < 4; c++) {
                u64* d = sm + OFF_SC + kqA * A_BLK + (4 * qA + c) * 8;
                { ulonglong2 s; s.x = ac[c][0]; s.y = ac[c][1]; *(ulonglong2*)d       = s; }
                { ulonglong2 s; s.x = ac[c][2]; s.y = ac[c][3]; *(ulonglong2*)(d + 2) = s; }
                { ulonglong2 s; s.x = ac[c][4]; s.y = ac[c][5]; *(ulonglong2*)(d + 4) = s; }
                d[6] = ac[c][6];
            }
        }
        __syncthreads();

        // ---- A-reduce + tanh -> A1[j][7 pairs]   (j = tid)
        {
            const u64* s0 = sm + OFF_SC + tid * 8;
            u64 acc[7];
            {
                ulonglong2 a = *(const ulonglong2*)s0;
                ulonglong2 b = *(const ulonglong2*)(s0 + 2);
                ulonglong2 c = *(const ulonglong2*)(s0 + 4);
                acc[0] = a.x; acc[1] = a.y; acc[2] = b.x; acc[3] = b.y;
                acc[4] = c.x; acc[5] = c.y; acc[6] = s0[6];
            }
            #pragma unroll
            for (int e = 1; e < 4; e++) {
                const u64* se = s0 + e * A_BLK;
                ulonglong2 a = *(const ulonglong2*)se;
                ulonglong2 b = *(const ulonglong2*)(se + 2);
                ulonglong2 c = *(const ulonglong2*)(se + 4);
                acc[0] = add2(acc[0], a.x); acc[1] = add2(acc[1], a.y);
                acc[2] = add2(acc[2], b.x); acc[3] = add2(acc[3], b.y);
                acc[4] = add2(acc[4], c.x); acc[5] = add2(acc[5], c.y);
                acc[6] = add2(acc[6], se[6]);
            }
            u64 o[7];
            #pragma unroll
            for (int i = 0; i < 7; i++) {
                float2 f = up2(acc[i]);
                o[i] = pk2(tanhf(f.x + bbA), tanhf(f.y + bbA));
            }
            u64* d = sm + OFF_A1 + tid * PSTR;
            { ulonglong2 s; s.x = o[0]; s.y = o[1]; *(ulonglong2*)d       = s; }
            { ulonglong2 s; s.x = o[2]; s.y = o[3]; *(ulonglong2*)(d + 2) = s; }
            { ulonglong2 s; s.x = o[4]; s.y = o[5]; *(ulonglong2*)(d + 4) = s; }
            d[6] = o[6];
        }
        __syncthreads();

        // ---- Phase B: partial f_ode[f][4qB..] = sum_{j in eighth} A1[f][j]*W2t[j][4qB..]
        {
            const int j0 = je * 32;
            const float4* w = (const float4*)g_W2t + qB;   // + j*32
            float4 buf[4];
            #pragma unroll
            for (int u = 0; u < 4; u++) buf[u] = __ldg(w + (j0 + u) * 32);
            u64 ac[4][7];
            #pragma unroll
            for (int c = 0; c < 4; c++)
                #pragma unroll
                for (int i = 0; i < 7; i++) ac[c][i] = 0ull;
            for (int jj = 0; jj < 32; jj += 4) {
                #pragma unroll
                for (int u = 0; u < 4; u++) {
                    float4 wv = buf[u];
                    buf[u] = __ldg(w + (j0 + jj + u + 4) * 32);   // ring prefetch (padded)
                    u64 wd[4] = { pk2(wv.x, wv.x), pk2(wv.y, wv.y),
                                  pk2(wv.z, wv.z), pk2(wv.w, wv.w) };
                    const u64* ar = sm + OFF_A1 + (j0 + jj + u) * PSTR;
                    ulonglong2 t0 = *(const ulonglong2*)ar;
                    ulonglong2 t1 = *(const ulonglong2*)(ar + 2);
                    ulonglong2 t2 = *(const ulonglong2*)(ar + 4);
                    u64 hv[7] = { t0.x, t0.y, t1.x, t1.y, t2.x, t2.y, ar[6] };
                    #pragma unroll
                    for (int c = 0; c < 4; c++)
                        #pragma unroll
                        for (int i = 0; i < 7; i++) ac[c][i] = fma2(hv[i], wd[c], ac[c][i]);
                }
            }
            #pragma unroll
            for (int c = 0; c < 4; c++) {
                u64* d = sm + OFF_SC + je * B_BLK + (4 * qB + c) * 8;
                { ulonglong2 s; s.x = ac[c][0]; s.y = ac[c][1]; *(ulonglong2*)d       = s; }
                { ulonglong2 s; s.x = ac[c][2]; s.y = ac[c][3]; *(ulonglong2*)(d + 2) = s; }
                { ulonglong2 s; s.x = ac[c][4]; s.y = ac[c][5]; *(ulonglong2*)(d + 4) = s; }
                d[6] = ac[c][6];
            }
        }
        __syncthreads();

        // ---- ODE update: h += dt * (sum of 8 B-partials + b2)
        {
            const int kk = tid >> 1, ph = tid & 1;
            u64* hrow = sm + OFF_HS + kk * PSTR;
            if (ph == 0) {
                const u64* bp = sm + OFF_SC + kk * 8;
                u64 s0, s1, s2, s3;
                {
                    ulonglong2 a = *(const ulonglong2*)bp;
                    ulonglong2 b = *(const ulonglong2*)(bp + 2);
                    s0 = a.x; s1 = a.y; s2 = b.x; s3 = b.y;
                }
                #pragma unroll
                for (int e = 1; e < 8; e++) {
                    const u64* se = bp + e * B_BLK;
                    ulonglong2 a = *(const ulonglong2*)se;
                    ulonglong2 b = *(const ulonglong2*)(se + 2);
                    s0 = add2(s0, a.x); s1 = add2(s1, a.y);
                    s2 = add2(s2, b.x); s3 = add2(s3, b.y);
                }
                ulonglong2 h01 = *(const ulonglong2*)hrow;
                ulonglong2 h23 = *(const ulonglong2*)(hrow + 2);
                float2 hv, sv;
                sv = up2(s0); hv = up2(h01.x);
                hv.x = fmaf(dt, sv.x + bbO, hv.x); hv.y = fmaf(dt, sv.y + bbO, hv.y);
                h01.x = pk2(hv.x, hv.y);
                sv = up2(s1); hv = up2(h01.y);
                hv.x = fmaf(dt, sv.x + bbO, hv.x); hv.y = fmaf(dt, sv.y + bbO, hv.y);
                h01.y = pk2(hv.x, hv.y);
                sv = up2(s2); hv = up2(h23.x);
                hv.x = fmaf(dt, sv.x + bbO, hv.x); hv.y = fmaf(dt, sv.y + bbO, hv.y);
                h23.x = pk2(hv.x, hv.y);
                sv = up2(s3); hv = up2(h23.y);
                hv.x = fmaf(dt, sv.x + bbO, hv.x); hv.y = fmaf(dt, sv.y + bbO, hv.y);
                h23.y = pk2(hv.x, hv.y);
                *(ulonglong2*)hrow       = h01;
                *(ulonglong2*)(hrow + 2) = h23;
            } else {
                const u64* bp = sm + OFF_SC + kk * 8 + 4;
                u64 s0, s1, s2;
                {
                    ulonglong2 a = *(const ulonglong2*)bp;
                    s0 = a.x; s1 = a.y; s2 = bp[2];
                }
                #pragma unroll
                for (int e = 1; e < 8; e++) {
                    const u64* se = bp + e * B_BLK;
                    ulonglong2 a = *(const ulonglong2*)se;
                    s0 = add2(s0, a.x); s1 = add2(s1, a.y); s2 = add2(s2, se[2]);
                }
                ulonglong2 h45 = *(const ulonglong2*)(hrow + 4);
                u64 h6 = hrow[6];
                float2 hv, sv;
                sv = up2(s0); hv = up2(h45.x);
                hv.x = fmaf(dt, sv.x + bbO, hv.x); hv.y = fmaf(dt, sv.y + bbO, hv.y);
                h45.x = pk2(hv.x, hv.y);
                sv = up2(s1); hv = up2(h45.y);
                hv.x = fmaf(dt, sv.x + bbO, hv.x); hv.y = fmaf(dt, sv.y + bbO, hv.y);
                h45.y = pk2(hv.x, hv.y);
                sv = up2(s2); hv = up2(h6);
                hv.x = fmaf(dt, sv.x + bbO, hv.x); hv.y = fmaf(dt, sv.y + bbO, hv.y);
                h6 = pk2(hv.x, hv.y);
                *(ulonglong2*)(hrow + 4) = h45;
                hrow[6] = h6;
            }
        }
        __syncthreads();

        // ---- Phase C: partial gh[f][{p,p+128,p+256}] over k-half (quad weight LDG)
        {
            const int k0 = kh * 64;
            const float4* w = (const float4*)g_Wht2 + p;   // + k*128
            float4 buf[4];
            #pragma unroll
            for (int u = 0; u < 4; u++) buf[u] = __ldg(w + (k0 + u) * 128);
            u64 ar[7], az[7], an[7];
            #pragma unroll
            for (int i = 0; i < 7; i++) { ar[i] = 0ull; az[i] = 0ull; an[i] = 0ull; }
            for (int kk2 = 0; kk2 < 64; kk2 += 4) {
                #pragma unroll
                for (int u = 0; u < 4; u++) {
                    float4 wv = buf[u];
                    buf[u] = __ldg(w + (k0 + kk2 + u + 4) * 128);   // ring prefetch (padded)
                    u64 w0 = pk2(wv.x, wv.x), w1 = pk2(wv.y, wv.y), w2 = pk2(wv.z, wv.z);
                    const u64* hr = sm + OFF_HS + (k0 + kk2 + u) * PSTR;
                    ulonglong2 t0 = *(const ulonglong2*)hr;
                    ulonglong2 t1 = *(const ulonglong2*)(hr + 2);
                    ulonglong2 t2 = *(const ulonglong2*)(hr + 4);
                    u64 hv[7] = { t0.x, t0.y, t1.x, t1.y, t2.x, t2.y, hr[6] };
                    #pragma unroll
                    for (int i = 0; i < 7; i++) {
                        ar[i] = fma2(hv[i], w0, ar[i]);
                        az[i] = fma2(hv[i], w1, az[i]);
                        an[i] = fma2(hv[i], w2, an[i]);
                    }
                }
            }
            u64* base = sm + OFF_SC + kh * C_BLK;
            {
                u64* d = base + p * 8;
                { ulonglong2 s; s.x = ar[0]; s.y = ar[1]; *(ulonglong2*)d       = s; }
                { ulonglong2 s; s.x = ar[2]; s.y = ar[3]; *(ulonglong2*)(d + 2) = s; }
                { ulonglong2 s; s.x = ar[4]; s.y = ar[5]; *(ulonglong2*)(d + 4) = s; }
                d[6] = ar[6];
            }
            {
                u64* d = base + (p + 128) * 8;
                { ulonglong2 s; s.x = az[0]; s.y = az[1]; *(ulonglong2*)d       = s; }
                { ulonglong2 s; s.x = az[2]; s.y = az[3]; *(ulonglong2*)(d + 2) = s; }
                { ulonglong2 s; s.x = az[4]; s.y = az[5]; *(ulonglong2*)(d + 4) = s; }
                d[6] = az[6];
            }
            {
                u64* d = base + (p + 256) * 8;
                { ulonglong2 s; s.x = an[0]; s.y = an[1]; *(ulonglong2*)d       = s; }
                { ulonglong2 s; s.x = an[2]; s.y = an[3]; *(ulonglong2*)(d + 2) = s; }
                { ulonglong2 s; s.x = an[4]; s.y = an[5]; *(ulonglong2*)(d + 4) = s; }
                d[6] = an[6];
            }
        }
        __syncthreads();

        // ---- GRU gates + mask update (reduces the 2 C-partials inline)
        {
            const int b0 = OFF_SC + p * 8;
            const int f0 = fh ? 4 : 0;
            const int f1 = fh ? 7 : 4;
            for (int fp = f0; fp < f1; fp++) {
                float2 ghr = up2(add2(sm[b0 + fp],            sm[b0 + C_BLK + fp]));
                float2 ghz = up2(add2(sm[b0 + 128 * 8 + fp],  sm[b0 + C_BLK + 128 * 8 + fp]));
                float2 ghn = up2(add2(sm[b0 + 256 * 8 + fp],  sm[b0 + C_BLK + 256 * 8 + fp]));
                float2 hv  = up2(sm[OFF_HS + p * PSTR + fp]);
                {
                    float x = xob[2 * fp], m = xms[2 * fp];
                    float rr = sigm(fmaf(x, wir, bir) + ghr.x + brg);
                    float zz = sigm(fmaf(x, wiz, biz) + ghz.x + bzg);
                    float nn = tanhf(fmaf(x, win, binn) + rr * (ghn.x + bng));
                    float hc = (1.0f - zz) * nn + zz * hv.x;
                    hv.x = m * hc + (1.0f - m) * hv.x;
                }
                {
                    float x = xob[2 * fp + 1], m = xms[2 * fp + 1];
                    float rr = sigm(fmaf(x, wir, bir) + ghr.y + brg);
                    float zz = sigm(fmaf(x, wiz, biz) + ghz.y + bzg);
                    float nn = tanhf(fmaf(x, win, binn) + rr * (ghn.y + bng));
                    float hc = (1.0f - zz) * nn + zz * hv.y;
                    hv.y = m * hc + (1.0f - m) * hv.y;
                }
                sm[OFF_HS + p * PSTR + fp] = pk2(hv.x, hv.y);
            }
        }
        __syncthreads();
    }

    // ---- store final h : out[f_global][k]
    const float* hf = (const float*)(sm + OFF_HS);   // float idx: k*(2*PSTR) + f
    for (int idx = tid; idx < NF * LL; idx += NTH) {
        int f = idx >> 7, k = idx & 127;
        int fg = cta * NF + f;
        if (fg < FF) out[fg * LL + k] = hf[k * 2 * PSTR + f];
    }
}

extern "C" void kernel_launch(void* const* d_in, const int* in_sizes, int n_in,
                              void* d_out, int out_size) {
    const float* times = (const float*)d_in[0];
    const float* vals  = (const float*)d_in[1];
    const float* mask  = (const float*)d_in[2];
    const float* W1    = (const float*)d_in[3];
    const float* b1    = (const float*)d_in[4];
    const float* W2    = (const float*)d_in[5];
    const float* b2    = (const float*)d_in[6];
    const float* Wih   = (const float*)d_in[7];
    const float* bih   = (const float*)d_in[8];
    const float* Whh   = (const float*)d_in[9];
    const float* bhh   = (const float*)d_in[10];
    float* out = (float*)d_out;

    (void)in_sizes; (void)n_in; (void)out_size;

    cudaFuncSetAttribute(odernn_kernel,
                         cudaFuncAttributeMaxDynamicSharedMemorySize, SMEM_BYTES);

    prep_kernel<<<(LL * 512 + 255) / 256, 256>>>(W1, W2, Whh);
    odernn_kernel<<<NCTA, NTH, SMEM_BYTES>>>(times, vals, mask, b1, b2,
                                             Wih, bih, bhh, out);
}

// round 16
// speedup vs baseline: 1.3477x; 1.3477x over previous
#include <cuda_runtime.h>

#define TT   1024
#define FF   2048
#define LL   128
#define HH   256
#define GG   384
#define NF   16            // features per CTA (8 pairs)
#define NTH  256
#define NCTA 128           // 2048 / 16
#define PSTR 10            // pair-stride in u64 (8 pairs + 2 pad)

typedef unsigned long long u64;

// k-major transposed weights, padded for prefetch-ring overrun (no allocation)
__device__ float g_W1t[LL * HH + 2048];    // [k][j]  = W1[j][k]
__device__ float g_W2t[HH * LL + 2048];    // [j][k'] = W2[k'][j]
__device__ float g_Wht2[LL * 512 + 2048];  // [k][p][4] = {Whh[p][k], Whh[p+128][k], Whh[p+256][k], 0}

// shared-memory layout (u64 units)
#define OFF_HS   0                          // h: [k=128][10]   -> 1280
#define OFF_A1   1280                       // A1: [j=256][10]  -> 2560
#define OFF_SC   3840                       // partial scratch
#define AP_BLK   2304                       // A: [kh=2][jp=128][18]
#define BP_BLK   1152                       // B: [jq=4][kp=64][18]
#define CP_BLK   3840                       // C: [kh=2][p=128][30]
#define U64_CNT  11520
#define SMEM_BYTES (U64_CNT * 8 + 64 * 4)   // 92416 B

__device__ __forceinline__ u64 pk2(float lo, float hi) {
    u64 r; asm("mov.b64 %0, {%1, %2};" : "=l"(r) : "f"(lo), "f"(hi)); return r;
}
__device__ __forceinline__ float2 up2(u64 v) {
    float2 r; asm("mov.b64 {%0, %1}, %2;" : "=f"(r.x), "=f"(r.y) : "l"(v)); return r;
}
__device__ __forceinline__ u64 fma2(u64 a, u64 b, u64 c) {
    u64 d; asm("fma.rn.f32x2 %0, %1, %2, %3;" : "=l"(d) : "l"(a), "l"(b), "l"(c)); return d;
}
__device__ __forceinline__ u64 add2(u64 a, u64 b) {
    u64 d; asm("add.rn.f32x2 %0, %1, %2;" : "=l"(d) : "l"(a), "l"(b)); return d;
}
__device__ __forceinline__ float sigm(float x) { return 1.0f / (1.0f + expf(-x)); }

__global__ void prep_kernel(const float* __restrict__ W1,
                            const float* __restrict__ W2,
                            const float* __restrict__ Whh) {
    int i = blockIdx.x * blockDim.x + threadIdx.x;
    if (i < HH * LL) { int j = i / LL, k = i % LL; g_W1t[k * HH + j] = W1[i]; }
    if (i < LL * HH) { int k = i / HH, j = i % HH; g_W2t[j * LL + k] = W2[i]; }
    if (i < LL * 512) {
        int k = i >> 9, r = i & 511, p = r >> 2, c = r & 3;
        g_Wht2[i] = (c < 3) ? Whh[(c * LL + p) * LL + k] : 0.0f;
    }
}

__global__ __launch_bounds__(NTH, 1)
void odernn_kernel(const float* __restrict__ times,
                   const float* __restrict__ vals,
                   const float* __restrict__ mask,
                   const float* __restrict__ b1,
                   const float* __restrict__ b2,
                   const float* __restrict__ Wih,
                   const float* __restrict__ bih,
                   const float* __restrict__ bhh,
                   float* __restrict__ out)
{
    extern __shared__ u64 sm[];
    float* xob = (float*)(sm + U64_CNT);     // 16
    float* xms = (float*)(sm + U64_CNT) + 16;

    const int tid = threadIdx.x;
    const int cta = blockIdx.x;

    for (int i = tid; i < 128 * PSTR; i += NTH) sm[OFF_HS + i] = 0ull;   // h0 = 0

    // thread-resident constants
    const int jp  = tid & 127;           // phase-A j-pair
    const int kh  = tid >> 7;            // k-half (phases A, C)
    const int kp  = tid & 63;            // phase-B k'-pair
    const int jq  = tid >> 6;            // phase-B j-quarter
    const int p   = tid & 127;           // latent index (C / GRU)
    const int fh  = tid >> 7;            // GRU feature-half
    const float bbA = __ldg(b1 + tid);                    // A-reduce bias
    const float bbO = __ldg(b2 + (tid >> 1));             // ODE bias
    const float brg = __ldg(bhh + p), bzg = __ldg(bhh + p + 128), bng = __ldg(bhh + p + 256);
    const float wir = __ldg(Wih + p), wiz = __ldg(Wih + p + 128), win = __ldg(Wih + p + 256);
    const float bir = __ldg(bih + p), biz = __ldg(bih + p + 128), binn = __ldg(bih + p + 256);
    __syncthreads();

    for (int t = 0; t < TT; t++) {
        if (tid < NF) {
            long it = (long)(TT - 1 - t) * FF + (cta * NF + tid);
            xob[tid] = __ldg(vals + it);
            xms[tid] = __ldg(mask + it);
        }
        float dt = 0.0f;
        if (t > 0) dt = __ldg(times + (TT - t)) - __ldg(times + (TT - 1 - t));

        // ---- Phase A: partial a1[f][2jp..] = sum_{k in half} h[f][k]*W1t[k][2jp..]
        {
            const int k0 = kh * 64;
            const float2* w = (const float2*)g_W1t + jp;   // stride 128 float2 per k
            float2 buf[8];
            #pragma unroll
            for (int u = 0; u < 8; u++) buf[u] = __ldg(w + (k0 + u) * 128);
            u64 a0[8], a1v[8];
            #pragma unroll
            for (int i = 0; i < 8; i++) { a0[i] = 0ull; a1v[i] = 0ull; }
            for (int kk = 0; kk < 64; kk += 8) {
                #pragma unroll
                for (int u = 0; u < 8; u++) {
                    float2 wv = buf[u];
                    buf[u] = __ldg(w + (k0 + kk + u + 8) * 128);   // ring prefetch (padded)
                    u64 w0 = pk2(wv.x, wv.x), w1 = pk2(wv.y, wv.y);
                    const u64* hr = sm + OFF_HS + (k0 + kk + u) * PSTR;
                    ulonglong2 hA = *(const ulonglong2*)hr;
                    ulonglong2 hB = *(const ulonglong2*)(hr + 2);
                    ulonglong2 hC = *(const ulonglong2*)(hr + 4);
                    ulonglong2 hD = *(const ulonglong2*)(hr + 6);
                    a0[0] = fma2(hA.x, w0, a0[0]);  a1v[0] = fma2(hA.x, w1, a1v[0]);
                    a0[1] = fma2(hA.y, w0, a0[1]);  a1v[1] = fma2(hA.y, w1, a1v[1]);
                    a0[2] = fma2(hB.x, w0, a0[2]);  a1v[2] = fma2(hB.x, w1, a1v[2]);
                    a0[3] = fma2(hB.y, w0, a0[3]);  a1v[3] = fma2(hB.y, w1, a1v[3]);
                    a0[4] = fma2(hC.x, w0, a0[4]);  a1v[4] = fma2(hC.x, w1, a1v[4]);
                    a0[5] = fma2(hC.y, w0, a0[5]);  a1v[5] = fma2(hC.y, w1, a1v[5]);
                    a0[6] = fma2(hD.x, w0, a0[6]);  a1v[6] = fma2(hD.x, w1, a1v[6]);
                    a0[7] = fma2(hD.y, w0, a0[7]);  a1v[7] = fma2(hD.y, w1, a1v[7]);
                }
            }
            u64* d = sm + OFF_SC + kh * AP_BLK + jp * 18;
            #pragma unroll
            for (int i = 0; i < 4; i++) {
                ulonglong2 s; s.x = a0[2*i]; s.y = a0[2*i+1];
                *(ulonglong2*)(d + 2*i) = s;
            }
            #pragma unroll
            for (int i = 0; i < 4; i++) {
                ulonglong2 s; s.x = a1v[2*i]; s.y = a1v[2*i+1];
                *(ulonglong2*)(d + 8 + 2*i) = s;
            }
        }
        __syncthreads();

        // ---- A-reduce + tanh -> A1[j][8 pairs]   (j = tid)
        {
            const u64* s0 = sm + OFF_SC + (tid >> 1) * 18 + (tid & 1) * 8;
            ulonglong2 pA = *(const ulonglong2*)s0;
            ulonglong2 pB = *(const ulonglong2*)(s0 + 2);
            ulonglong2 pC = *(const ulonglong2*)(s0 + 4);
            ulonglong2 pD = *(const ulonglong2*)(s0 + 6);
            ulonglong2 qA = *(const ulonglong2*)(s0 + AP_BLK);
            ulonglong2 qB = *(const ulonglong2*)(s0 + AP_BLK + 2);
            ulonglong2 qC = *(const ulonglong2*)(s0 + AP_BLK + 4);
            ulonglong2 qD = *(const ulonglong2*)(s0 + AP_BLK + 6);
            float2 f0 = up2(add2(pA.x, qA.x)), f1 = up2(add2(pA.y, qA.y));
            float2 f2 = up2(add2(pB.x, qB.x)), f3 = up2(add2(pB.y, qB.y));
            float2 f4 = up2(add2(pC.x, qC.x)), f5 = up2(add2(pC.y, qC.y));
            float2 f6 = up2(add2(pD.x, qD.x)), f7 = up2(add2(pD.y, qD.y));
            ulonglong2 o0, o1, o2, o3;
            o0.x = pk2(tanhf(f0.x + bbA), tanhf(f0.y + bbA));
            o0.y = pk2(tanhf(f1.x + bbA), tanhf(f1.y + bbA));
            o1.x = pk2(tanhf(f2.x + bbA), tanhf(f2.y + bbA));
            o1.y = pk2(tanhf(f3.x + bbA), tanhf(f3.y + bbA));
            o2.x = pk2(tanhf(f4.x + bbA), tanhf(f4.y + bbA));
            o2.y = pk2(tanhf(f5.x + bbA), tanhf(f5.y + bbA));
            o3.x = pk2(tanhf(f6.x + bbA), tanhf(f6.y + bbA));
            o3.y = pk2(tanhf(f7.x + bbA), tanhf(f7.y + bbA));
            u64* d = sm + OFF_A1 + tid * PSTR;
            *(ulonglong2*)d       = o0;
            *(ulonglong2*)(d + 2) = o1;
            *(ulonglong2*)(d + 4) = o2;
            *(ulonglong2*)(d + 6) = o3;
        }
        __syncthreads();

        // ---- Phase B: partial f_ode[f][2kp..] = sum_{j in quarter} A1[f][j]*W2t[j][2kp..]
        {
            const int j0 = jq * 64;
            const float2* w = (const float2*)g_W2t + kp;   // stride 64 float2 per j
            float2 buf[8];
            #pragma unroll
            for (int u = 0; u < 8; u++) buf[u] = __ldg(w + (j0 + u) * 64);
            u64 a0[8], a1v[8];
            #pragma unroll
            for (int i = 0; i < 8; i++) { a0[i] = 0ull; a1v[i] = 0ull; }
            for (int jj = 0; jj < 64; jj += 8) {
                #pragma unroll
                for (int u = 0; u < 8; u++) {
                    float2 wv = buf[u];
                    buf[u] = __ldg(w + (j0 + jj + u + 8) * 64);    // ring prefetch (padded)
                    u64 w0 = pk2(wv.x, wv.x), w1 = pk2(wv.y, wv.y);
                    const u64* ar = sm + OFF_A1 + (j0 + jj + u) * PSTR;
                    ulonglong2 hA = *(const ulonglong2*)ar;
                    ulonglong2 hB = *(const ulonglong2*)(ar + 2);
                    ulonglong2 hC = *(const ulonglong2*)(ar + 4);
                    ulonglong2 hD = *(const ulonglong2*)(ar + 6);
                    a0[0] = fma2(hA.x, w0, a0[0]);  a1v[0] = fma2(hA.x, w1, a1v[0]);
                    a0[1] = fma2(hA.y, w0, a0[1]);  a1v[1] = fma2(hA.y, w1, a1v[1]);
                    a0[2] = fma2(hB.x, w0, a0[2]);  a1v[2] = fma2(hB.x, w1, a1v[2]);
                    a0[3] = fma2(hB.y, w0, a0[3]);  a1v[3] = fma2(hB.y, w1, a1v[3]);
                    a0[4] = fma2(hC.x, w0, a0[4]);  a1v[4] = fma2(hC.x, w1, a1v[4]);
                    a0[5] = fma2(hC.y, w0, a0[5]);  a1v[5] = fma2(hC.y, w1, a1v[5]);
                    a0[6] = fma2(hD.x, w0, a0[6]);  a1v[6] = fma2(hD.x, w1, a1v[6]);
                    a0[7] = fma2(hD.y, w0, a0[7]);  a1v[7] = fma2(hD.y, w1, a1v[7]);
                }
            }
            u64* d = sm + OFF_SC + jq * BP_BLK + kp * 18;
            #pragma unroll
            for (int i = 0; i < 4; i++) {
                ulonglong2 s; s.x = a0[2*i]; s.y = a0[2*i+1];
                *(ulonglong2*)(d + 2*i) = s;
            }
            #pragma unroll
            for (int i = 0; i < 4; i++) {
                ulonglong2 s; s.x = a1v[2*i]; s.y = a1v[2*i+1];
                *(ulonglong2*)(d + 8 + 2*i) = s;
            }
        }
        __syncthreads();

        // ---- ODE update: h += dt * (sum of 4 B-partials + b2)
        {
            const int kk = tid >> 1, ph = tid & 1;
            const u64* bp = sm + OFF_SC + (kk >> 1) * 18 + (kk & 1) * 8 + ph * 4;
            ulonglong2 x0 = *(const ulonglong2*)bp;
            ulonglong2 x1 = *(const ulonglong2*)(bp + 2);
            ulonglong2 y0 = *(const ulonglong2*)(bp + BP_BLK);
            ulonglong2 y1 = *(const ulonglong2*)(bp + BP_BLK + 2);
            ulonglong2 z0 = *(const ulonglong2*)(bp + 2 * BP_BLK);
            ulonglong2 z1 = *(const ulonglong2*)(bp + 2 * BP_BLK + 2);
            ulonglong2 u0 = *(const ulonglong2*)(bp + 3 * BP_BLK);
            ulonglong2 u1 = *(const ulonglong2*)(bp + 3 * BP_BLK + 2);
            u64 s0 = add2(add2(x0.x, y0.x), add2(z0.x, u0.x));
            u64 s1 = add2(add2(x0.y, y0.y), add2(z0.y, u0.y));
            u64 s2 = add2(add2(x1.x, y1.x), add2(z1.x, u1.x));
            u64 s3 = add2(add2(x1.y, y1.y), add2(z1.y, u1.y));
            u64* hp = sm + OFF_HS + kk * PSTR + ph * 4;
            ulonglong2 h01 = *(const ulonglong2*)hp;
            ulonglong2 h23 = *(const ulonglong2*)(hp + 2);
            float2 hv, sv;
            sv = up2(s0); hv = up2(h01.x);
            hv.x = fmaf(dt, sv.x + bbO, hv.x); hv.y = fmaf(dt, sv.y + bbO, hv.y);
            h01.x = pk2(hv.x, hv.y);
            sv = up2(s1); hv = up2(h01.y);
            hv.x = fmaf(dt, sv.x + bbO, hv.x); hv.y = fmaf(dt, sv.y + bbO, hv.y);
            h01.y = pk2(hv.x, hv.y);
            sv = up2(s2); hv = up2(h23.x);
            hv.x = fmaf(dt, sv.x + bbO, hv.x); hv.y = fmaf(dt, sv.y + bbO, hv.y);
            h23.x = pk2(hv.x, hv.y);
            sv = up2(s3); hv = up2(h23.y);
            hv.x = fmaf(dt, sv.x + bbO, hv.x); hv.y = fmaf(dt, sv.y + bbO, hv.y);
            h23.y = pk2(hv.x, hv.y);
            *(ulonglong2*)hp       = h01;
            *(ulonglong2*)(hp + 2) = h23;
        }
        __syncthreads();

        // ---- Phase C: partial gh[f][g] for g = p, p+128, p+256 over k-half
        //      (quad-packed weights: one LDG.128 per k instead of 3x LDG.32)
        {
            const int k0 = kh * 64;
            const float4* w = (const float4*)g_Wht2 + p;   // + k*128
            float4 buf[4];
            #pragma unroll
            for (int u = 0; u < 4; u++) buf[u] = __ldg(w + (k0 + u) * 128);
            u64 ar[8], az[8], an[8];
            #pragma unroll
            for (int i = 0; i < 8; i++) { ar[i] = 0ull; az[i] = 0ull; an[i] = 0ull; }
            for (int kk2 = 0; kk2 < 64; kk2 += 4) {
                #pragma unroll
                for (int u = 0; u < 4; u++) {
                    float4 wv = buf[u];
                    buf[u] = __ldg(w + (k0 + kk2 + u + 4) * 128);   // ring prefetch (padded)
                    u64 w0 = pk2(wv.x, wv.x), w1 = pk2(wv.y, wv.y), w2 = pk2(wv.z, wv.z);
                    const u64* hr = sm + OFF_HS + (k0 + kk2 + u) * PSTR;
                    ulonglong2 hA = *(const ulonglong2*)hr;
                    ulonglong2 hB = *(const ulonglong2*)(hr + 2);
                    ulonglong2 hC = *(const ulonglong2*)(hr + 4);
                    ulonglong2 hD = *(const ulonglong2*)(hr + 6);
                    ar[0] = fma2(hA.x, w0, ar[0]); az[0] = fma2(hA.x, w1, az[0]); an[0] = fma2(hA.x, w2, an[0]);
                    ar[1] = fma2(hA.y, w0, ar[1]); az[1] = fma2(hA.y, w1, az[1]); an[1] = fma2(hA.y, w2, an[1]);
                    ar[2] = fma2(hB.x, w0, ar[2]); az[2] = fma2(hB.x, w1, az[2]); an[2] = fma2(hB.x, w2, an[2]);
                    ar[3] = fma2(hB.y, w0, ar[3]); az[3] = fma2(hB.y, w1, az[3]); an[3] = fma2(hB.y, w2, an[3]);
                    ar[4] = fma2(hC.x, w0, ar[4]); az[4] = fma2(hC.x, w1, az[4]); an[4] = fma2(hC.x, w2, an[4]);
                    ar[5] = fma2(hC.y, w0, ar[5]); az[5] = fma2(hC.y, w1, az[5]); an[5] = fma2(hC.y, w2, an[5]);
                    ar[6] = fma2(hD.x, w0, ar[6]); az[6] = fma2(hD.x, w1, az[6]); an[6] = fma2(hD.x, w2, an[6]);
                    ar[7] = fma2(hD.y, w0, ar[7]); az[7] = fma2(hD.y, w1, az[7]); an[7] = fma2(hD.y, w2, an[7]);
                }
            }
            u64* d = sm + OFF_SC + kh * CP_BLK + p * 30;
            #pragma unroll
            for (int i = 0; i < 4; i++) {
                ulonglong2 s; s.x = ar[2*i]; s.y = ar[2*i+1];
                *(ulonglong2*)(d + 2*i) = s;
            }
            #pragma unroll
            for (int i = 0; i < 4; i++) {
                ulonglong2 s; s.x = az[2*i]; s.y = az[2*i+1];
                *(ulonglong2*)(d + 10 + 2*i) = s;
            }
            #pragma unroll
            for (int i = 0; i < 4; i++) {
                ulonglong2 s; s.x = an[2*i]; s.y = an[2*i+1];
                *(ulonglong2*)(d + 20 + 2*i) = s;
            }
        }
        __syncthreads();

        // ---- GRU gates + mask update (reduces C partials inline)
        {
            const int b0 = OFF_SC + p * 30;
            #pragma unroll
            for (int q = 0; q < 4; q++) {
                const int fp = fh * 4 + q;
                float2 ghr = up2(add2(sm[b0 + fp],      sm[b0 + CP_BLK + fp]));
                float2 ghz = up2(add2(sm[b0 + 10 + fp], sm[b0 + CP_BLK + 10 + fp]));
                float2 ghn = up2(add2(sm[b0 + 20 + fp], sm[b0 + CP_BLK + 20 + fp]));
                float2 hv  = up2(sm[OFF_HS + p * PSTR + fp]);
                {
                    float x = xob[2 * fp], m = xms[2 * fp];
                    float rr = sigm(fmaf(x, wir, bir) + ghr.x + brg);
                    float zz = sigm(fmaf(x, wiz, biz) + ghz.x + bzg);
                    float nn = tanhf(fmaf(x, win, binn) + rr * (ghn.x + bng));
                    float hc = (1.0f - zz) * nn + zz * hv.x;
                    hv.x = m * hc + (1.0f - m) * hv.x;
                }
                {
                    float x = xob[2 * fp + 1], m = xms[2 * fp + 1];
                    float rr = sigm(fmaf(x, wir, bir) + ghr.y + brg);
                    float zz = sigm(fmaf(x, wiz, biz) + ghz.y + bzg);
                    float nn = tanhf(fmaf(x, win, binn) + rr * (ghn.y + bng));
                    float hc = (1.0f - zz) * nn + zz * hv.y;
                    hv.y = m * hc + (1.0f - m) * hv.y;
                }
                sm[OFF_HS + p * PSTR + fp] = pk2(hv.x, hv.y);
            }
        }
        __syncthreads();
    }

    // ---- store final h : out[f_global][k]
    const float* hf = (const float*)(sm + OFF_HS);   // float idx: k*(2*PSTR) + f
    for (int idx = tid; idx < NF * LL; idx += NTH) {
        int f = idx >> 7, k = idx & 127;
        out[(cta * NF + f) * LL + k] = hf[k * 2 * PSTR + f];
    }
}

extern "C" void kernel_launch(void* const* d_in, const int* in_sizes, int n_in,
                              void* d_out, int out_size) {
    const float* times = (const float*)d_in[0];
    const float* vals  = (const float*)d_in[1];
    const float* mask  = (const float*)d_in[2];
    const float* W1    = (const float*)d_in[3];
    const float* b1    = (const float*)d_in[4];
    const float* W2    = (const float*)d_in[5];
    const float* b2    = (const float*)d_in[6];
    const float* Wih   = (const float*)d_in[7];
    const float* bih   = (const float*)d_in[8];
    const float* Whh   = (const float*)d_in[9];
    const float* bhh   = (const float*)d_in[10];
    float* out = (float*)d_out;

    (void)in_sizes; (void)n_in; (void)out_size;

    cudaFuncSetAttribute(odernn_kernel,
                         cudaFuncAttributeMaxDynamicSharedMemorySize, SMEM_BYTES);

    prep_kernel<<<(LL * 512 + 255) / 256, 256>>>(W1, W2, Whh);
    odernn_kernel<<<NCTA, NTH, SMEM_BYTES>>>(times, vals, mask, b1, b2,
                                             Wih, bih, bhh, out);
}